// round 11
// baseline (speedup 1.0000x reference)
#include <cuda_runtime.h>
#include <cuda_bf16.h>
#include <math.h>
#include <stdint.h>

#define N_NODES 100000
#define FEAT    256
#define HEADS   8
#define HEAD_DIM 32
#define E_EDGES 800000
#define SMAX    56

// ---------------- scratch (no cudaMalloc allowed) ----------------
__device__ float g_q[(size_t)N_NODES * FEAT];
__device__ float g_k[(size_t)N_NODES * FEAT];
__device__ float g_v[(size_t)N_NODES * FEAT];
__device__ __nv_bfloat16 g_a2[(size_t)N_NODES * 512];
__device__ __nv_bfloat16 g_acc2[(size_t)N_NODES * 512];
__device__ __nv_bfloat16 g_w2[4][(size_t)256 * 768];
// edge sort
__device__ int g_cnt[N_NODES];
__device__ int g_incl[N_NODES];
__device__ int g_off[N_NODES + 1];
__device__ int g_cur[N_NODES];
__device__ int g_eid[E_EDGES];
__device__ int g_srcs[E_EDGES];
__device__ float g_biasp[(size_t)E_EDGES * HEADS];
__device__ int g_bsum[128];

// ================= PTX helpers =================
__device__ __forceinline__ uint32_t smem_to_u32(const void* p) {
    uint32_t a;
    asm("{ .reg .u64 t; cvta.to.shared.u64 t, %1; cvt.u32.u64 %0, t; }" : "=r"(a) : "l"(p));
    return a;
}

#define LDSM_X4(r0, r1, r2, r3, addr) \
    asm volatile("ldmatrix.sync.aligned.m8n8.x4.shared.b16 {%0,%1,%2,%3}, [%4];" \
        : "=r"(r0), "=r"(r1), "=r"(r2), "=r"(r3) : "r"(addr))

#define MMA_16816(c, a0, a1, a2, a3, b0, b1) \
    asm volatile("mma.sync.aligned.m16n8k16.row.col.f32.bf16.bf16.f32 " \
        "{%0,%1,%2,%3}, {%4,%5,%6,%7}, {%8,%9}, {%0,%1,%2,%3};" \
        : "+f"((c)[0]), "+f"((c)[1]), "+f"((c)[2]), "+f"((c)[3]) \
        : "r"(a0), "r"(a1), "r"(a2), "r"(a3), "r"(b0), "r"(b1))

__device__ __forceinline__ void cp_async16(uint32_t dst, const void* src, uint32_t src_size) {
    asm volatile("cp.async.cg.shared.global [%0], [%1], 16, %2;"
        :: "r"(dst), "l"(src), "r"(src_size) : "memory");
}
#define CP_ASYNC_COMMIT() asm volatile("cp.async.commit_group;" ::: "memory")
#define CP_ASYNC_WAIT_GROUP(n) asm volatile("cp.async.wait_group %0;" :: "n"(n) : "memory")

// ---------------- fp32 -> bf16 hi/lo split (nodes) ----------------
__global__ void conv_split_kernel(const float* __restrict__ X,
                                  __nv_bfloat16* __restrict__ Y,
                                  int rows) {
    int i = blockIdx.x * blockDim.x + threadIdx.x;
    int tot = rows * 64;
    if (i >= tot) return;
    int row = i >> 6, qq = i & 63;
    float4 x = ((const float4*)X)[i];
    __nv_bfloat16 h0 = __float2bfloat16(x.x), h1 = __float2bfloat16(x.y);
    __nv_bfloat16 h2 = __float2bfloat16(x.z), h3 = __float2bfloat16(x.w);
    __nv_bfloat16 l0 = __float2bfloat16(x.x - __bfloat162float(h0));
    __nv_bfloat16 l1 = __float2bfloat16(x.y - __bfloat162float(h1));
    __nv_bfloat16 l2 = __float2bfloat16(x.z - __bfloat162float(h2));
    __nv_bfloat16 l3 = __float2bfloat16(x.w - __bfloat162float(h3));
    uint32_t hA = ((uint32_t)__bfloat16_as_ushort(h1) << 16) | __bfloat16_as_ushort(h0);
    uint32_t hB = ((uint32_t)__bfloat16_as_ushort(h3) << 16) | __bfloat16_as_ushort(h2);
    uint32_t lA = ((uint32_t)__bfloat16_as_ushort(l1) << 16) | __bfloat16_as_ushort(l0);
    uint32_t lB = ((uint32_t)__bfloat16_as_ushort(l3) << 16) | __bfloat16_as_ushort(l2);
    size_t base = (size_t)row * 512 + qq * 4;
    *(uint2*)(Y + base)       = make_uint2(hA, hB);
    *(uint2*)(Y + base + 256) = make_uint2(lA, lB);
}

// ---------------- W -> W' = [Whi | Wlo | Whi], 4 mats fused ----------------
__global__ void conv_w_kernel(const float* __restrict__ W0, const float* __restrict__ W1,
                              const float* __restrict__ W2p, const float* __restrict__ W3,
                              __nv_bfloat16* __restrict__ OUT) {
    int i = blockIdx.x * blockDim.x + threadIdx.x;
    if (i >= 256 * 768) return;
    int which = blockIdx.y;
    const float* W = (which == 0) ? W0 : (which == 1) ? W1 : (which == 2) ? W2p : W3;
    int n = i / 768, kc = i % 768;
    int sk = (kc < 256) ? kc : ((kc < 512) ? kc - 256 : kc - 512);
    float w = W[n * 256 + sk];
    __nv_bfloat16 hi = __float2bfloat16(w);
    __nv_bfloat16 res;
    if (kc < 256 || kc >= 512) res = hi;
    else res = __float2bfloat16(w - __bfloat162float(hi));
    OUT[(size_t)which * 256 * 768 + (size_t)n * 768 + kc] = res;
}

// ---------------- HMMA GEMM (multi-output): gridDim.x = 2*nmat, 3-stage pipeline ----------------
#define NCHUNK 12
#define ROWB   144
#define ATILE  (128 * ROWB)
#define STAGE  (2 * ATILE)
#define GSMEM_BYTES (3 * STAGE)

__global__ __launch_bounds__(256, 2) void gemm_mma_kernel(
        const __nv_bfloat16* __restrict__ A2,
        const __nv_bfloat16* __restrict__ Wall,
        float* __restrict__ C0, float* __restrict__ C1, float* __restrict__ C2,
        int M, float scale0) {
    extern __shared__ __align__(16) char smem[];
    const uint32_t sbase = smem_to_u32(smem);

    const int tid = threadIdx.x;
    const int lane = tid & 31;
    const int wid = tid >> 5;
    const int warp_m = wid & 3;
    const int warp_n = wid >> 2;
    const int row0 = blockIdx.y * 128;
    const int wsel = blockIdx.x >> 1;
    const int col0 = (blockIdx.x & 1) * 128;
    const __nv_bfloat16* W2 = Wall + (size_t)wsel * 256 * 768;
    float* C = (wsel == 0) ? C0 : ((wsel == 1) ? C1 : C2);
    const float outScale = (wsel == 0) ? scale0 : 1.0f;

    const int lq = tid & 7;
    const int lr0 = tid >> 3;

    const uint32_t a_off = (uint32_t)((lane & 15) * ROWB + ((lane & 16) ? 16 : 0));
    const uint32_t b_off = (uint32_t)(((lane & 7) + ((lane & 16) ? 8 : 0)) * ROWB +
                                      ((lane & 8) ? 16 : 0));

    float cfr[2][8][4];
#pragma unroll
    for (int mi = 0; mi < 2; mi++)
#pragma unroll
        for (int ni = 0; ni < 8; ni++)
#pragma unroll
            for (int j = 0; j < 4; j++) cfr[mi][ni][j] = 0.0f;

    auto issue_loads = [&](int c) {
        const int stage_idx = c % 3;
        const int srcoff = ((c < 8) ? 0 : 256) + (c & 3) * 64;
        const uint32_t sa = sbase + stage_idx * STAGE;
        const uint32_t sb = sa + ATILE;
#pragma unroll
        for (int it = 0; it < 4; it++) {
            int r = lr0 + it * 32;
            int gr = row0 + r;
            uint32_t ok = (gr < M) ? 16u : 0u;
            int grc = (gr < M) ? gr : 0;
            cp_async16(sa + r * ROWB + lq * 16,
                       A2 + (size_t)grc * 512 + srcoff + lq * 8, ok);
            cp_async16(sb + r * ROWB + lq * 16,
                       W2 + (size_t)(col0 + r) * 768 + c * 64 + lq * 8, 16u);
        }
        CP_ASYNC_COMMIT();
    };

    issue_loads(0);
    issue_loads(1);

    for (int c = 0; c < NCHUNK; c++) {
        CP_ASYNC_WAIT_GROUP(1);
        __syncthreads();
        if (c + 2 < NCHUNK) issue_loads(c + 2);

        const uint32_t sa = sbase + (c % 3) * STAGE + (warp_m * 32) * ROWB + a_off;
        const uint32_t sb = sbase + (c % 3) * STAGE + ATILE + (warp_n * 64) * ROWB + b_off;

#pragma unroll
        for (int kk = 0; kk < 4; kk++) {
            uint32_t a[2][4];
#pragma unroll
            for (int mi = 0; mi < 2; mi++)
                LDSM_X4(a[mi][0], a[mi][1], a[mi][2], a[mi][3],
                        sa + mi * 16 * ROWB + kk * 32);
            uint32_t b[4][4];
#pragma unroll
            for (int nt = 0; nt < 4; nt++)
                LDSM_X4(b[nt][0], b[nt][1], b[nt][2], b[nt][3],
                        sb + nt * 16 * ROWB + kk * 32);
#pragma unroll
            for (int mi = 0; mi < 2; mi++)
#pragma unroll
                for (int nt = 0; nt < 4; nt++) {
                    MMA_16816(cfr[mi][nt * 2 + 0],
                              a[mi][0], a[mi][1], a[mi][2], a[mi][3],
                              b[nt][0], b[nt][1]);
                    MMA_16816(cfr[mi][nt * 2 + 1],
                              a[mi][0], a[mi][1], a[mi][2], a[mi][3],
                              b[nt][2], b[nt][3]);
                }
        }
    }

    const int rbase = row0 + warp_m * 32 + (lane >> 2);
    const int cbase = col0 + warp_n * 64 + (lane & 3) * 2;
#pragma unroll
    for (int mi = 0; mi < 2; mi++) {
#pragma unroll
        for (int ni = 0; ni < 8; ni++) {
            int r = rbase + mi * 16;
            int cc = cbase + ni * 8;
            if (r < M) {
                float2 o0 = make_float2(cfr[mi][ni][0] * outScale, cfr[mi][ni][1] * outScale);
                *(float2*)&C[(size_t)r * FEAT + cc] = o0;
            }
            if (r + 8 < M) {
                float2 o1 = make_float2(cfr[mi][ni][2] * outScale, cfr[mi][ni][3] * outScale);
                *(float2*)&C[(size_t)(r + 8) * FEAT + cc] = o1;
            }
        }
    }
}

// ================= edge sort: counting sort by dst =================
__global__ void zero_cnt_kernel(int* cnt, int n) {
    int i = blockIdx.x * blockDim.x + threadIdx.x;
    if (i < n) cnt[i] = 0;
}
__global__ void hist_kernel(const int* __restrict__ dst, int* cnt, int E) {
    int e = blockIdx.x * blockDim.x + threadIdx.x;
    if (e < E) atomicAdd(&cnt[dst[e]], 1);
}
__global__ void scan1_kernel(const int* __restrict__ cnt, int* incl, int* bsum, int n) {
    __shared__ int sm[1024];
    int i = blockIdx.x * 1024 + threadIdx.x;
    int val = (i < n) ? cnt[i] : 0;
    sm[threadIdx.x] = val;
    __syncthreads();
#pragma unroll
    for (int off = 1; off < 1024; off <<= 1) {
        int t = (threadIdx.x >= off) ? sm[threadIdx.x - off] : 0;
        __syncthreads();
        sm[threadIdx.x] += t;
        __syncthreads();
    }
    if (i < n) incl[i] = sm[threadIdx.x];
    if (threadIdx.x == 1023) bsum[blockIdx.x] = sm[1023];
}
__global__ void scan2_kernel(int* bsum, int nb) {
    __shared__ int sm[128];
    int t = threadIdx.x;
    int v = (t < nb) ? bsum[t] : 0;
    sm[t] = v;
    __syncthreads();
#pragma unroll
    for (int off = 1; off < 128; off <<= 1) {
        int u = (t >= off) ? sm[t - off] : 0;
        __syncthreads();
        sm[t] += u;
        __syncthreads();
    }
    if (t < nb) bsum[t] = sm[t] - v;
}
__global__ void scan3_kernel(const int* __restrict__ incl, const int* __restrict__ bsum,
                             const int* __restrict__ cnt, int* off, int* cur, int n) {
    int i = blockIdx.x * blockDim.x + threadIdx.x;
    if (i == 0) off[0] = 0;
    if (i < n) {
        int o = incl[i] + bsum[i >> 10];
        off[i + 1] = o;
        cur[i] = o - cnt[i];
    }
}
__global__ void scatter_kernel(const int* __restrict__ dst, const int* __restrict__ src,
                               int* cur, int* eid, int* srcs, int E) {
    int e = blockIdx.x * blockDim.x + threadIdx.x;
    if (e < E) {
        int pos = atomicAdd(&cur[dst[e]], 1);
        eid[pos] = e;
        srcs[pos] = src[e];
    }
}
__global__ void bias_perm_kernel(const float* __restrict__ bias,
                                 const int* __restrict__ eid,
                                 float* __restrict__ biasp, int E) {
    int i = blockIdx.x * blockDim.x + threadIdx.x;
    if (i >= 2 * E) return;
    int idx = i >> 1, half = i & 1;
    int e = eid[idx];
    float4 vals = *(const float4*)(bias + (size_t)e * HEADS + half * 4);
    *(float4*)(biasp + (size_t)idx * HEADS + half * 4) = vals;
}

// ================= fused edge kernel: warp per dst, TWO-PASS, 2-edge unrolled =================
__global__ __launch_bounds__(256) void edge_fused_kernel(
        const float* __restrict__ q,
        const float* __restrict__ k,
        const float* __restrict__ v,
        const float* __restrict__ biasp,
        const int* __restrict__ srcs,
        const int* __restrict__ off,
        __nv_bfloat16* __restrict__ acc2,
        int N) {
    __shared__ float slog[8][SMAX * 8];
    const unsigned FULL = 0xffffffffu;
    int gw = (int)((blockIdx.x * (size_t)blockDim.x + threadIdx.x) >> 5);
    int lane = threadIdx.x & 31;
    int wib = threadIdx.x >> 5;
    if (gw >= N) return;
    const int d = gw;
    const int beg = off[d], end = off[d + 1];
    const int deg = end - beg;
    const int h = lane >> 2;

    const float4* qp = (const float4*)(q + (size_t)d * FEAT);
    float4 q0, q1;
    float mh = -INFINITY;
    const bool fits = (deg <= SMAX);

    if (deg > 0) {
        q0 = qp[lane * 2];
        q1 = qp[lane * 2 + 1];
        // ---- pass 1: logits + max (staged src, 2-edge unroll for MLP) ----
        for (int base = 0; base < deg; base += 32) {
            int cnt = min(32, deg - base);
            int s_l = 0;
            if (lane < cnt) s_l = __ldg(&srcs[beg + base + lane]);
            int i = 0;
            for (; i + 2 <= cnt; i += 2) {
                int sn0 = __shfl_sync(FULL, s_l, i);
                int sn1 = __shfl_sync(FULL, s_l, i + 1);
                const float4* kp0 = (const float4*)(k + (size_t)sn0 * FEAT);
                const float4* kp1 = (const float4*)(k + (size_t)sn1 * FEAT);
                float4 a0 = kp0[lane * 2], a1 = kp0[lane * 2 + 1];
                float4 b0 = kp1[lane * 2], b1 = kp1[lane * 2 + 1];
                float d0 = q0.x * a0.x + q0.y * a0.y + q0.z * a0.z + q0.w * a0.w
                         + q1.x * a1.x + q1.y * a1.y + q1.z * a1.z + q1.w * a1.w;
                float d1 = q0.x * b0.x + q0.y * b0.y + q0.z * b0.z + q0.w * b0.w
                         + q1.x * b1.x + q1.y * b1.y + q1.z * b1.z + q1.w * b1.w;
                d0 += __shfl_xor_sync(FULL, d0, 1);
                d1 += __shfl_xor_sync(FULL, d1, 1);
                d0 += __shfl_xor_sync(FULL, d0, 2);
                d1 += __shfl_xor_sync(FULL, d1, 2);
                float l0 = d0 + __ldg(&biasp[(size_t)(beg + base + i) * HEADS + h]);
                float l1 = d1 + __ldg(&biasp[(size_t)(beg + base + i + 1) * HEADS + h]);
                mh = fmaxf(mh, fmaxf(l0, l1));
                if (fits && (lane & 3) == 0) {
                    slog[wib][(base + i) * 8 + h] = l0;
                    slog[wib][(base + i + 1) * 8 + h] = l1;
                }
            }
            if (i < cnt) {
                int sn = __shfl_sync(FULL, s_l, i);
                const float4* kp = (const float4*)(k + (size_t)sn * FEAT);
                float4 k0 = kp[lane * 2], k1 = kp[lane * 2 + 1];
                float ds = q0.x * k0.x + q0.y * k0.y + q0.z * k0.z + q0.w * k0.w
                         + q1.x * k1.x + q1.y * k1.y + q1.z * k1.z + q1.w * k1.w;
                ds += __shfl_xor_sync(FULL, ds, 1);
                ds += __shfl_xor_sync(FULL, ds, 2);
                float l = ds + __ldg(&biasp[(size_t)(beg + base + i) * HEADS + h]);
                mh = fmaxf(mh, l);
                if (fits && (lane & 3) == 0) slog[wib][(base + i) * 8 + h] = l;
            }
        }
    }

    // ---- pass 2: exp, sum, weighted v accumulate (2-edge unroll) ----
    float acc[8] = {0, 0, 0, 0, 0, 0, 0, 0};
    float ssum = 0.0f;
    for (int base = 0; base < deg; base += 32) {
        int cnt = min(32, deg - base);
        int s_l = 0;
        if (lane < cnt) s_l = __ldg(&srcs[beg + base + lane]);
        int i = 0;
        for (; i + 2 <= cnt && fits; i += 2) {
            int sn0 = __shfl_sync(FULL, s_l, i);
            int sn1 = __shfl_sync(FULL, s_l, i + 1);
            float l0 = slog[wib][(base + i) * 8 + h];
            float l1 = slog[wib][(base + i + 1) * 8 + h];
            const float4* vp0 = (const float4*)(v + (size_t)sn0 * FEAT);
            const float4* vp1 = (const float4*)(v + (size_t)sn1 * FEAT);
            float4 x0 = vp0[lane * 2], x1 = vp0[lane * 2 + 1];
            float4 y0 = vp1[lane * 2], y1 = vp1[lane * 2 + 1];
            float a0 = __expf(l0 - mh);
            float a1 = __expf(l1 - mh);
            ssum += a0 + a1;
            acc[0] = fmaf(a0, x0.x, acc[0]); acc[0] = fmaf(a1, y0.x, acc[0]);
            acc[1] = fmaf(a0, x0.y, acc[1]); acc[1] = fmaf(a1, y0.y, acc[1]);
            acc[2] = fmaf(a0, x0.z, acc[2]); acc[2] = fmaf(a1, y0.z, acc[2]);
            acc[3] = fmaf(a0, x0.w, acc[3]); acc[3] = fmaf(a1, y0.w, acc[3]);
            acc[4] = fmaf(a0, x1.x, acc[4]); acc[4] = fmaf(a1, y1.x, acc[4]);
            acc[5] = fmaf(a0, x1.y, acc[5]); acc[5] = fmaf(a1, y1.y, acc[5]);
            acc[6] = fmaf(a0, x1.z, acc[6]); acc[6] = fmaf(a1, y1.z, acc[6]);
            acc[7] = fmaf(a0, x1.w, acc[7]); acc[7] = fmaf(a1, y1.w, acc[7]);
        }
        for (; i < cnt; i++) {
            int sn = __shfl_sync(FULL, s_l, i);
            float l;
            if (fits) {
                l = slog[wib][(base + i) * 8 + h];
            } else {
                const float4* kp = (const float4*)(k + (size_t)sn * FEAT);
                float4 k0 = kp[lane * 2], k1 = kp[lane * 2 + 1];
                float ds = q0.x * k0.x + q0.y * k0.y + q0.z * k0.z + q0.w * k0.w
                         + q1.x * k1.x + q1.y * k1.y + q1.z * k1.z + q1.w * k1.w;
                ds += __shfl_xor_sync(FULL, ds, 1);
                ds += __shfl_xor_sync(FULL, ds, 2);
                l = ds + __ldg(&biasp[(size_t)(beg + base + i) * HEADS + h]);
            }
            float a = __expf(l - mh);
            ssum += a;
            const float4* vp = (const float4*)(v + (size_t)sn * FEAT);
            float4 v0 = vp[lane * 2], v1 = vp[lane * 2 + 1];
            acc[0] = fmaf(a, v0.x, acc[0]);
            acc[1] = fmaf(a, v0.y, acc[1]);
            acc[2] = fmaf(a, v0.z, acc[2]);
            acc[3] = fmaf(a, v0.w, acc[3]);
            acc[4] = fmaf(a, v1.x, acc[4]);
            acc[5] = fmaf(a, v1.y, acc[5]);
            acc[6] = fmaf(a, v1.z, acc[6]);
            acc[7] = fmaf(a, v1.w, acc[7]);
        }
    }

    float r = (deg > 0) ? (1.0f / ssum) : 0.0f;

    float o[8];
#pragma unroll
    for (int j = 0; j < 8; j++) o[j] = acc[j] * r;
    __nv_bfloat16 hi[8], lo[8];
#pragma unroll
    for (int j = 0; j < 8; j++) {
        hi[j] = __float2bfloat16(o[j]);
        lo[j] = __float2bfloat16(o[j] - __bfloat162float(hi[j]));
    }
    uint4 hv, lv;
    hv.x = ((uint32_t)__bfloat16_as_ushort(hi[1]) << 16) | __bfloat16_as_ushort(hi[0]);
    hv.y = ((uint32_t)__bfloat16_as_ushort(hi[3]) << 16) | __bfloat16_as_ushort(hi[2]);
    hv.z = ((uint32_t)__bfloat16_as_ushort(hi[5]) << 16) | __bfloat16_as_ushort(hi[4]);
    hv.w = ((uint32_t)__bfloat16_as_ushort(hi[7]) << 16) | __bfloat16_as_ushort(hi[6]);
    lv.x = ((uint32_t)__bfloat16_as_ushort(lo[1]) << 16) | __bfloat16_as_ushort(lo[0]);
    lv.y = ((uint32_t)__bfloat16_as_ushort(lo[3]) << 16) | __bfloat16_as_ushort(lo[2]);
    lv.z = ((uint32_t)__bfloat16_as_ushort(lo[5]) << 16) | __bfloat16_as_ushort(lo[4]);
    lv.w = ((uint32_t)__bfloat16_as_ushort(lo[7]) << 16) | __bfloat16_as_ushort(lo[6]);
    *(uint4*)(acc2 + (size_t)d * 512 + lane * 8)       = hv;
    *(uint4*)(acc2 + (size_t)d * 512 + 256 + lane * 8) = lv;
}

// ---------------- launch ----------------
extern "C" void kernel_launch(void* const* d_in, const int* in_sizes, int n_in,
                              void* d_out, int out_size) {
    const float* nfeat = (const float*)d_in[0];
    const float* attn_bias = (const float*)d_in[1];
    const float* Wq = (const float*)d_in[2];
    const float* Wk = (const float*)d_in[3];
    const float* Wv = (const float*)d_in[4];
    const float* Wo = (const float*)d_in[5];
    const int* src = (const int*)d_in[6];
    const int* dst = (const int*)d_in[7];
    float* out = (float*)d_out;

    int N = in_sizes[0] / FEAT;
    int E = in_sizes[6];

    float *q, *k, *v, *biasp;
    __nv_bfloat16 *a2, *acc2, *w2;
    int *cnt, *incl, *off, *cur, *eid, *srcs, *bsum;
    cudaGetSymbolAddress((void**)&q, g_q);
    cudaGetSymbolAddress((void**)&k, g_k);
    cudaGetSymbolAddress((void**)&v, g_v);
    cudaGetSymbolAddress((void**)&a2, g_a2);
    cudaGetSymbolAddress((void**)&acc2, g_acc2);
    cudaGetSymbolAddress((void**)&w2, g_w2);
    cudaGetSymbolAddress((void**)&cnt, g_cnt);
    cudaGetSymbolAddress((void**)&incl, g_incl);
    cudaGetSymbolAddress((void**)&off, g_off);
    cudaGetSymbolAddress((void**)&cur, g_cur);
    cudaGetSymbolAddress((void**)&eid, g_eid);
    cudaGetSymbolAddress((void**)&srcs, g_srcs);
    cudaGetSymbolAddress((void**)&biasp, g_biasp);
    cudaGetSymbolAddress((void**)&bsum, g_bsum);

    cudaFuncSetAttribute(gemm_mma_kernel, cudaFuncAttributeMaxDynamicSharedMemorySize, GSMEM_BYTES);

    static cudaStream_t s_sort = nullptr;
    static cudaEvent_t ev_fork = nullptr, ev_join = nullptr;
    if (!s_sort) {
        cudaStreamCreateWithFlags(&s_sort, cudaStreamNonBlocking);
        cudaEventCreateWithFlags(&ev_fork, cudaEventDisableTiming);
        cudaEventCreateWithFlags(&ev_join, cudaEventDisableTiming);
    }

    // ---- fork: edge counting sort + permutes on side stream ----
    cudaEventRecord(ev_fork, 0);
    cudaStreamWaitEvent(s_sort, ev_fork, 0);
    int nb1024 = (N + 1023) / 1024;
    zero_cnt_kernel<<<(N + 255) / 256, 256, 0, s_sort>>>(cnt, N);
    hist_kernel<<<(E + 255) / 256, 256, 0, s_sort>>>(dst, cnt, E);
    scan1_kernel<<<nb1024, 1024, 0, s_sort>>>(cnt, incl, bsum, N);
    scan2_kernel<<<1, 128, 0, s_sort>>>(bsum, nb1024);
    scan3_kernel<<<(N + 255) / 256, 256, 0, s_sort>>>(incl, bsum, cnt, off, cur, N);
    scatter_kernel<<<(E + 255) / 256, 256, 0, s_sort>>>(dst, src, cur, eid, srcs, E);
    bias_perm_kernel<<<(2 * E + 255) / 256, 256, 0, s_sort>>>(attn_bias, eid, biasp, E);
    cudaEventRecord(ev_join, s_sort);

    // ---- main stream: conversions + fused QKV projection ----
    int cblocks = (N * 64 + 255) / 256;
    conv_split_kernel<<<cblocks, 256>>>(nfeat, a2, N);
    dim3 wgrid((256 * 768 + 255) / 256, 4);
    conv_w_kernel<<<wgrid, 256>>>(Wq, Wk, Wv, Wo, w2);

    const float invScaling = 5.656854249492381f;  // sqrt(HEAD_DIM): reference DIVIDES q by scaling
    dim3 qkvgrid(6, (N + 127) / 128);
    gemm_mma_kernel<<<qkvgrid, 256, GSMEM_BYTES>>>(a2, w2, q, k, v, N, invScaling);

    // ---- join sort before edge kernel ----
    cudaStreamWaitEvent(0, ev_join, 0);

    // ---- fused edge softmax + aggregate (two-pass, 2-edge unrolled) ----
    int fblocks = (N + 7) / 8;
    edge_fused_kernel<<<fblocks, 256>>>(q, k, v, biasp, srcs, off, acc2, N);

    // ---- final projection (single matrix: Wo slot) ----
    dim3 ogrid(2, (N + 127) / 128);
    gemm_mma_kernel<<<ogrid, 256, GSMEM_BYTES>>>(acc2, w2 + 3 * (size_t)256 * 768,
                                                 out, nullptr, nullptr, N, 1.0f);
}

// round 12
// speedup vs baseline: 1.0136x; 1.0136x over previous
#include <cuda_runtime.h>
#include <cuda_bf16.h>
#include <math.h>
#include <stdint.h>

#define N_NODES 100000
#define FEAT    256
#define HEADS   8
#define HEAD_DIM 32
#define E_EDGES 800000
#define SMAX    56

// ---------------- scratch (no cudaMalloc allowed) ----------------
__device__ float g_q[(size_t)N_NODES * FEAT];
__device__ float g_k[(size_t)N_NODES * FEAT];
__device__ float g_v[(size_t)N_NODES * FEAT];
__device__ __nv_bfloat16 g_a2[(size_t)N_NODES * 512];
__device__ __nv_bfloat16 g_acc2[(size_t)N_NODES * 512];
__device__ __nv_bfloat16 g_w2[4][(size_t)256 * 768];
// edge sort
__device__ int g_cnt[N_NODES];
__device__ int g_incl[N_NODES];
__device__ int g_off[N_NODES + 1];
__device__ int g_cur[N_NODES];
__device__ int g_eid[E_EDGES];
__device__ int g_srcs[E_EDGES];
__device__ float g_biasp[(size_t)E_EDGES * HEADS];
__device__ int g_bsum[128];

// ================= PTX helpers =================
__device__ __forceinline__ uint32_t smem_to_u32(const void* p) {
    uint32_t a;
    asm("{ .reg .u64 t; cvta.to.shared.u64 t, %1; cvt.u32.u64 %0, t; }" : "=r"(a) : "l"(p));
    return a;
}

#define LDSM_X4(r0, r1, r2, r3, addr) \
    asm volatile("ldmatrix.sync.aligned.m8n8.x4.shared.b16 {%0,%1,%2,%3}, [%4];" \
        : "=r"(r0), "=r"(r1), "=r"(r2), "=r"(r3) : "r"(addr))

#define MMA_16816(c, a0, a1, a2, a3, b0, b1) \
    asm volatile("mma.sync.aligned.m16n8k16.row.col.f32.bf16.bf16.f32 " \
        "{%0,%1,%2,%3}, {%4,%5,%6,%7}, {%8,%9}, {%0,%1,%2,%3};" \
        : "+f"((c)[0]), "+f"((c)[1]), "+f"((c)[2]), "+f"((c)[3]) \
        : "r"(a0), "r"(a1), "r"(a2), "r"(a3), "r"(b0), "r"(b1))

__device__ __forceinline__ void cp_async16(uint32_t dst, const void* src, uint32_t src_size) {
    asm volatile("cp.async.cg.shared.global [%0], [%1], 16, %2;"
        :: "r"(dst), "l"(src), "r"(src_size) : "memory");
}
#define CP_ASYNC_COMMIT() asm volatile("cp.async.commit_group;" ::: "memory")
#define CP_ASYNC_WAIT_GROUP(n) asm volatile("cp.async.wait_group %0;" :: "n"(n) : "memory")

// ---------------- fp32 -> bf16 hi/lo split (nodes) ----------------
__global__ void conv_split_kernel(const float* __restrict__ X,
                                  __nv_bfloat16* __restrict__ Y,
                                  int rows) {
    int i = blockIdx.x * blockDim.x + threadIdx.x;
    int tot = rows * 64;
    if (i >= tot) return;
    int row = i >> 6, qq = i & 63;
    float4 x = ((const float4*)X)[i];
    __nv_bfloat16 h0 = __float2bfloat16(x.x), h1 = __float2bfloat16(x.y);
    __nv_bfloat16 h2 = __float2bfloat16(x.z), h3 = __float2bfloat16(x.w);
    __nv_bfloat16 l0 = __float2bfloat16(x.x - __bfloat162float(h0));
    __nv_bfloat16 l1 = __float2bfloat16(x.y - __bfloat162float(h1));
    __nv_bfloat16 l2 = __float2bfloat16(x.z - __bfloat162float(h2));
    __nv_bfloat16 l3 = __float2bfloat16(x.w - __bfloat162float(h3));
    uint32_t hA = ((uint32_t)__bfloat16_as_ushort(h1) << 16) | __bfloat16_as_ushort(h0);
    uint32_t hB = ((uint32_t)__bfloat16_as_ushort(h3) << 16) | __bfloat16_as_ushort(h2);
    uint32_t lA = ((uint32_t)__bfloat16_as_ushort(l1) << 16) | __bfloat16_as_ushort(l0);
    uint32_t lB = ((uint32_t)__bfloat16_as_ushort(l3) << 16) | __bfloat16_as_ushort(l2);
    size_t base = (size_t)row * 512 + qq * 4;
    *(uint2*)(Y + base)       = make_uint2(hA, hB);
    *(uint2*)(Y + base + 256) = make_uint2(lA, lB);
}

// ---------------- W -> W' = [Whi | Wlo | Whi], 4 mats fused ----------------
__global__ void conv_w_kernel(const float* __restrict__ W0, const float* __restrict__ W1,
                              const float* __restrict__ W2p, const float* __restrict__ W3,
                              __nv_bfloat16* __restrict__ OUT) {
    int i = blockIdx.x * blockDim.x + threadIdx.x;
    if (i >= 256 * 768) return;
    int which = blockIdx.y;
    const float* W = (which == 0) ? W0 : (which == 1) ? W1 : (which == 2) ? W2p : W3;
    int n = i / 768, kc = i % 768;
    int sk = (kc < 256) ? kc : ((kc < 512) ? kc - 256 : kc - 512);
    float w = W[n * 256 + sk];
    __nv_bfloat16 hi = __float2bfloat16(w);
    __nv_bfloat16 res;
    if (kc < 256 || kc >= 512) res = hi;
    else res = __float2bfloat16(w - __bfloat162float(hi));
    OUT[(size_t)which * 256 * 768 + (size_t)n * 768 + kc] = res;
}

// ---------------- HMMA GEMM (multi-output): gridDim.x = 2*nmat, 3-stage pipeline ----------------
#define NCHUNK 12
#define ROWB   144
#define ATILE  (128 * ROWB)
#define STAGE  (2 * ATILE)
#define GSMEM_BYTES (3 * STAGE)

__global__ __launch_bounds__(256, 2) void gemm_mma_kernel(
        const __nv_bfloat16* __restrict__ A2,
        const __nv_bfloat16* __restrict__ Wall,
        float* __restrict__ C0, float* __restrict__ C1, float* __restrict__ C2,
        int M, float scale0) {
    extern __shared__ __align__(16) char smem[];
    const uint32_t sbase = smem_to_u32(smem);

    const int tid = threadIdx.x;
    const int lane = tid & 31;
    const int wid = tid >> 5;
    const int warp_m = wid & 3;
    const int warp_n = wid >> 2;
    const int row0 = blockIdx.y * 128;
    const int wsel = blockIdx.x >> 1;
    const int col0 = (blockIdx.x & 1) * 128;
    const __nv_bfloat16* W2 = Wall + (size_t)wsel * 256 * 768;
    float* C = (wsel == 0) ? C0 : ((wsel == 1) ? C1 : C2);
    const float outScale = (wsel == 0) ? scale0 : 1.0f;

    const int lq = tid & 7;
    const int lr0 = tid >> 3;

    const uint32_t a_off = (uint32_t)((lane & 15) * ROWB + ((lane & 16) ? 16 : 0));
    const uint32_t b_off = (uint32_t)(((lane & 7) + ((lane & 16) ? 8 : 0)) * ROWB +
                                      ((lane & 8) ? 16 : 0));

    float cfr[2][8][4];
#pragma unroll
    for (int mi = 0; mi < 2; mi++)
#pragma unroll
        for (int ni = 0; ni < 8; ni++)
#pragma unroll
            for (int j = 0; j < 4; j++) cfr[mi][ni][j] = 0.0f;

    auto issue_loads = [&](int c) {
        const int stage_idx = c % 3;
        const int srcoff = ((c < 8) ? 0 : 256) + (c & 3) * 64;
        const uint32_t sa = sbase + stage_idx * STAGE;
        const uint32_t sb = sa + ATILE;
#pragma unroll
        for (int it = 0; it < 4; it++) {
            int r = lr0 + it * 32;
            int gr = row0 + r;
            uint32_t ok = (gr < M) ? 16u : 0u;
            int grc = (gr < M) ? gr : 0;
            cp_async16(sa + r * ROWB + lq * 16,
                       A2 + (size_t)grc * 512 + srcoff + lq * 8, ok);
            cp_async16(sb + r * ROWB + lq * 16,
                       W2 + (size_t)(col0 + r) * 768 + c * 64 + lq * 8, 16u);
        }
        CP_ASYNC_COMMIT();
    };

    issue_loads(0);
    issue_loads(1);

    for (int c = 0; c < NCHUNK; c++) {
        CP_ASYNC_WAIT_GROUP(1);
        __syncthreads();
        if (c + 2 < NCHUNK) issue_loads(c + 2);

        const uint32_t sa = sbase + (c % 3) * STAGE + (warp_m * 32) * ROWB + a_off;
        const uint32_t sb = sbase + (c % 3) * STAGE + ATILE + (warp_n * 64) * ROWB + b_off;

#pragma unroll
        for (int kk = 0; kk < 4; kk++) {
            uint32_t a[2][4];
#pragma unroll
            for (int mi = 0; mi < 2; mi++)
                LDSM_X4(a[mi][0], a[mi][1], a[mi][2], a[mi][3],
                        sa + mi * 16 * ROWB + kk * 32);
            uint32_t b[4][4];
#pragma unroll
            for (int nt = 0; nt < 4; nt++)
                LDSM_X4(b[nt][0], b[nt][1], b[nt][2], b[nt][3],
                        sb + nt * 16 * ROWB + kk * 32);
#pragma unroll
            for (int mi = 0; mi < 2; mi++)
#pragma unroll
                for (int nt = 0; nt < 4; nt++) {
                    MMA_16816(cfr[mi][nt * 2 + 0],
                              a[mi][0], a[mi][1], a[mi][2], a[mi][3],
                              b[nt][0], b[nt][1]);
                    MMA_16816(cfr[mi][nt * 2 + 1],
                              a[mi][0], a[mi][1], a[mi][2], a[mi][3],
                              b[nt][2], b[nt][3]);
                }
        }
    }

    const int rbase = row0 + warp_m * 32 + (lane >> 2);
    const int cbase = col0 + warp_n * 64 + (lane & 3) * 2;
#pragma unroll
    for (int mi = 0; mi < 2; mi++) {
#pragma unroll
        for (int ni = 0; ni < 8; ni++) {
            int r = rbase + mi * 16;
            int cc = cbase + ni * 8;
            if (r < M) {
                float2 o0 = make_float2(cfr[mi][ni][0] * outScale, cfr[mi][ni][1] * outScale);
                *(float2*)&C[(size_t)r * FEAT + cc] = o0;
            }
            if (r + 8 < M) {
                float2 o1 = make_float2(cfr[mi][ni][2] * outScale, cfr[mi][ni][3] * outScale);
                *(float2*)&C[(size_t)(r + 8) * FEAT + cc] = o1;
            }
        }
    }
}

// ================= edge sort: counting sort by dst =================
__global__ void zero_cnt_kernel(int* cnt, int n) {
    int i = blockIdx.x * blockDim.x + threadIdx.x;
    if (i < n) cnt[i] = 0;
}
__global__ void hist_kernel(const int* __restrict__ dst, int* cnt, int E) {
    int e = blockIdx.x * blockDim.x + threadIdx.x;
    if (e < E) atomicAdd(&cnt[dst[e]], 1);
}
__global__ void scan1_kernel(const int* __restrict__ cnt, int* incl, int* bsum, int n) {
    __shared__ int sm[1024];
    int i = blockIdx.x * 1024 + threadIdx.x;
    int val = (i < n) ? cnt[i] : 0;
    sm[threadIdx.x] = val;
    __syncthreads();
#pragma unroll
    for (int off = 1; off < 1024; off <<= 1) {
        int t = (threadIdx.x >= off) ? sm[threadIdx.x - off] : 0;
        __syncthreads();
        sm[threadIdx.x] += t;
        __syncthreads();
    }
    if (i < n) incl[i] = sm[threadIdx.x];
    if (threadIdx.x == 1023) bsum[blockIdx.x] = sm[1023];
}
__global__ void scan2_kernel(int* bsum, int nb) {
    __shared__ int sm[128];
    int t = threadIdx.x;
    int v = (t < nb) ? bsum[t] : 0;
    sm[t] = v;
    __syncthreads();
#pragma unroll
    for (int off = 1; off < 128; off <<= 1) {
        int u = (t >= off) ? sm[t - off] : 0;
        __syncthreads();
        sm[t] += u;
        __syncthreads();
    }
    if (t < nb) bsum[t] = sm[t] - v;
}
__global__ void scan3_kernel(const int* __restrict__ incl, const int* __restrict__ bsum,
                             const int* __restrict__ cnt, int* off, int* cur, int n) {
    int i = blockIdx.x * blockDim.x + threadIdx.x;
    if (i == 0) off[0] = 0;
    if (i < n) {
        int o = incl[i] + bsum[i >> 10];
        off[i + 1] = o;
        cur[i] = o - cnt[i];
    }
}
__global__ void scatter_kernel(const int* __restrict__ dst, const int* __restrict__ src,
                               int* cur, int* eid, int* srcs, int E) {
    int e = blockIdx.x * blockDim.x + threadIdx.x;
    if (e < E) {
        int pos = atomicAdd(&cur[dst[e]], 1);
        eid[pos] = e;
        srcs[pos] = src[e];
    }
}
__global__ void bias_perm_kernel(const float* __restrict__ bias,
                                 const int* __restrict__ eid,
                                 float* __restrict__ biasp, int E) {
    int i = blockIdx.x * blockDim.x + threadIdx.x;
    if (i >= 2 * E) return;
    int idx = i >> 1, half = i & 1;
    int e = eid[idx];
    float4 vals = *(const float4*)(bias + (size_t)e * HEADS + half * 4);
    *(float4*)(biasp + (size_t)idx * HEADS + half * 4) = vals;
}

// ================= fused edge kernel: warp per dst, TWO-PASS (round-9 optimum) =================
__global__ __launch_bounds__(256) void edge_fused_kernel(
        const float* __restrict__ q,
        const float* __restrict__ k,
        const float* __restrict__ v,
        const float* __restrict__ biasp,
        const int* __restrict__ srcs,
        const int* __restrict__ off,
        __nv_bfloat16* __restrict__ acc2,
        int N) {
    __shared__ float slog[8][SMAX * 8];
    const unsigned FULL = 0xffffffffu;
    int gw = (int)((blockIdx.x * (size_t)blockDim.x + threadIdx.x) >> 5);
    int lane = threadIdx.x & 31;
    int wib = threadIdx.x >> 5;
    if (gw >= N) return;
    const int d = gw;
    const int beg = off[d], end = off[d + 1];
    const int deg = end - beg;
    const int h = lane >> 2;

    const float4* qp = (const float4*)(q + (size_t)d * FEAT);
    float4 q0, q1;
    float mh = -INFINITY;
    const bool fits = (deg <= SMAX);

    if (deg > 0) {
        q0 = qp[lane * 2];
        q1 = qp[lane * 2 + 1];
        for (int base = 0; base < deg; base += 32) {
            int cnt = min(32, deg - base);
            int s_l = 0;
            if (lane < cnt) s_l = __ldg(&srcs[beg + base + lane]);
            for (int i = 0; i < cnt; i++) {
                int sn = __shfl_sync(FULL, s_l, i);
                const float4* kp = (const float4*)(k + (size_t)sn * FEAT);
                float4 k0 = kp[lane * 2], k1 = kp[lane * 2 + 1];
                float ds = q0.x * k0.x + q0.y * k0.y + q0.z * k0.z + q0.w * k0.w
                         + q1.x * k1.x + q1.y * k1.y + q1.z * k1.z + q1.w * k1.w;
                ds += __shfl_xor_sync(FULL, ds, 1);
                ds += __shfl_xor_sync(FULL, ds, 2);
                float l = ds + __ldg(&biasp[(size_t)(beg + base + i) * HEADS + h]);
                mh = fmaxf(mh, l);
                if (fits && (lane & 3) == 0) slog[wib][(base + i) * 8 + h] = l;
            }
        }
    }

    float acc[8] = {0, 0, 0, 0, 0, 0, 0, 0};
    float ssum = 0.0f;
    for (int base = 0; base < deg; base += 32) {
        int cnt = min(32, deg - base);
        int s_l = 0;
        if (lane < cnt) s_l = __ldg(&srcs[beg + base + lane]);
        for (int i = 0; i < cnt; i++) {
            int sn = __shfl_sync(FULL, s_l, i);
            float l;
            if (fits) {
                l = slog[wib][(base + i) * 8 + h];
            } else {
                const float4* kp = (const float4*)(k + (size_t)sn * FEAT);
                float4 k0 = kp[lane * 2], k1 = kp[lane * 2 + 1];
                float ds = q0.x * k0.x + q0.y * k0.y + q0.z * k0.z + q0.w * k0.w
                         + q1.x * k1.x + q1.y * k1.y + q1.z * k1.z + q1.w * k1.w;
                ds += __shfl_xor_sync(FULL, ds, 1);
                ds += __shfl_xor_sync(FULL, ds, 2);
                l = ds + __ldg(&biasp[(size_t)(beg + base + i) * HEADS + h]);
            }
            float a = __expf(l - mh);
            ssum += a;
            const float4* vp = (const float4*)(v + (size_t)sn * FEAT);
            float4 v0 = vp[lane * 2], v1 = vp[lane * 2 + 1];
            acc[0] = fmaf(a, v0.x, acc[0]);
            acc[1] = fmaf(a, v0.y, acc[1]);
            acc[2] = fmaf(a, v0.z, acc[2]);
            acc[3] = fmaf(a, v0.w, acc[3]);
            acc[4] = fmaf(a, v1.x, acc[4]);
            acc[5] = fmaf(a, v1.y, acc[5]);
            acc[6] = fmaf(a, v1.z, acc[6]);
            acc[7] = fmaf(a, v1.w, acc[7]);
        }
    }

    float r = (deg > 0) ? (1.0f / ssum) : 0.0f;

    float o[8];
#pragma unroll
    for (int j = 0; j < 8; j++) o[j] = acc[j] * r;
    __nv_bfloat16 hi[8], lo[8];
#pragma unroll
    for (int j = 0; j < 8; j++) {
        hi[j] = __float2bfloat16(o[j]);
        lo[j] = __float2bfloat16(o[j] - __bfloat162float(hi[j]));
    }
    uint4 hv, lv;
    hv.x = ((uint32_t)__bfloat16_as_ushort(hi[1]) << 16) | __bfloat16_as_ushort(hi[0]);
    hv.y = ((uint32_t)__bfloat16_as_ushort(hi[3]) << 16) | __bfloat16_as_ushort(hi[2]);
    hv.z = ((uint32_t)__bfloat16_as_ushort(hi[5]) << 16) | __bfloat16_as_ushort(hi[4]);
    hv.w = ((uint32_t)__bfloat16_as_ushort(hi[7]) << 16) | __bfloat16_as_ushort(hi[6]);
    lv.x = ((uint32_t)__bfloat16_as_ushort(lo[1]) << 16) | __bfloat16_as_ushort(lo[0]);
    lv.y = ((uint32_t)__bfloat16_as_ushort(lo[3]) << 16) | __bfloat16_as_ushort(lo[2]);
    lv.z = ((uint32_t)__bfloat16_as_ushort(lo[5]) << 16) | __bfloat16_as_ushort(lo[4]);
    lv.w = ((uint32_t)__bfloat16_as_ushort(lo[7]) << 16) | __bfloat16_as_ushort(lo[6]);
    *(uint4*)(acc2 + (size_t)d * 512 + lane * 8)       = hv;
    *(uint4*)(acc2 + (size_t)d * 512 + 256 + lane * 8) = lv;
}

// ---------------- launch ----------------
extern "C" void kernel_launch(void* const* d_in, const int* in_sizes, int n_in,
                              void* d_out, int out_size) {
    const float* nfeat = (const float*)d_in[0];
    const float* attn_bias = (const float*)d_in[1];
    const float* Wq = (const float*)d_in[2];
    const float* Wk = (const float*)d_in[3];
    const float* Wv = (const float*)d_in[4];
    const float* Wo = (const float*)d_in[5];
    const int* src = (const int*)d_in[6];
    const int* dst = (const int*)d_in[7];
    float* out = (float*)d_out;

    int N = in_sizes[0] / FEAT;
    int E = in_sizes[6];

    float *q, *k, *v, *biasp;
    __nv_bfloat16 *a2, *acc2, *w2;
    int *cnt, *incl, *off, *cur, *eid, *srcs, *bsum;
    cudaGetSymbolAddress((void**)&q, g_q);
    cudaGetSymbolAddress((void**)&k, g_k);
    cudaGetSymbolAddress((void**)&v, g_v);
    cudaGetSymbolAddress((void**)&a2, g_a2);
    cudaGetSymbolAddress((void**)&acc2, g_acc2);
    cudaGetSymbolAddress((void**)&w2, g_w2);
    cudaGetSymbolAddress((void**)&cnt, g_cnt);
    cudaGetSymbolAddress((void**)&incl, g_incl);
    cudaGetSymbolAddress((void**)&off, g_off);
    cudaGetSymbolAddress((void**)&cur, g_cur);
    cudaGetSymbolAddress((void**)&eid, g_eid);
    cudaGetSymbolAddress((void**)&srcs, g_srcs);
    cudaGetSymbolAddress((void**)&biasp, g_biasp);
    cudaGetSymbolAddress((void**)&bsum, g_bsum);

    cudaFuncSetAttribute(gemm_mma_kernel, cudaFuncAttributeMaxDynamicSharedMemorySize, GSMEM_BYTES);

    static cudaStream_t s_sort = nullptr;
    static cudaEvent_t ev_fork = nullptr, ev_join = nullptr, ev_w = nullptr;
    if (!s_sort) {
        cudaStreamCreateWithFlags(&s_sort, cudaStreamNonBlocking);
        cudaEventCreateWithFlags(&ev_fork, cudaEventDisableTiming);
        cudaEventCreateWithFlags(&ev_join, cudaEventDisableTiming);
        cudaEventCreateWithFlags(&ev_w, cudaEventDisableTiming);
    }

    // ---- fork: conv_w first (needed by QKV GEMM), then sort chain on side stream ----
    cudaEventRecord(ev_fork, 0);
    cudaStreamWaitEvent(s_sort, ev_fork, 0);
    dim3 wgrid((256 * 768 + 255) / 256, 4);
    conv_w_kernel<<<wgrid, 256, 0, s_sort>>>(Wq, Wk, Wv, Wo, w2);
    cudaEventRecord(ev_w, s_sort);
    int nb1024 = (N + 1023) / 1024;
    zero_cnt_kernel<<<(N + 255) / 256, 256, 0, s_sort>>>(cnt, N);
    hist_kernel<<<(E + 255) / 256, 256, 0, s_sort>>>(dst, cnt, E);
    scan1_kernel<<<nb1024, 1024, 0, s_sort>>>(cnt, incl, bsum, N);
    scan2_kernel<<<1, 128, 0, s_sort>>>(bsum, nb1024);
    scan3_kernel<<<(N + 255) / 256, 256, 0, s_sort>>>(incl, bsum, cnt, off, cur, N);
    scatter_kernel<<<(E + 255) / 256, 256, 0, s_sort>>>(dst, src, cur, eid, srcs, E);
    bias_perm_kernel<<<(2 * E + 255) / 256, 256, 0, s_sort>>>(attn_bias, eid, biasp, E);
    cudaEventRecord(ev_join, s_sort);

    // ---- main stream: conv_split overlaps conv_w, then fused QKV projection ----
    int cblocks = (N * 64 + 255) / 256;
    conv_split_kernel<<<cblocks, 256>>>(nfeat, a2, N);
    cudaStreamWaitEvent(0, ev_w, 0);

    const float invScaling = 5.656854249492381f;  // sqrt(HEAD_DIM): reference DIVIDES q by scaling
    dim3 qkvgrid(6, (N + 127) / 128);
    gemm_mma_kernel<<<qkvgrid, 256, GSMEM_BYTES>>>(a2, w2, q, k, v, N, invScaling);

    // ---- join sort before edge kernel ----
    cudaStreamWaitEvent(0, ev_join, 0);

    // ---- fused edge softmax + aggregate (two-pass) ----
    int fblocks = (N + 7) / 8;
    edge_fused_kernel<<<fblocks, 256>>>(q, k, v, biasp, srcs, off, acc2, N);

    // ---- final projection (single matrix: Wo slot) ----
    dim3 ogrid(2, (N + 127) / 128);
    gemm_mma_kernel<<<ogrid, 256, GSMEM_BYTES>>>(acc2, w2 + 3 * (size_t)256 * 768,
                                                 out, nullptr, nullptr, N, 1.0f);
}

// round 13
// speedup vs baseline: 1.0294x; 1.0155x over previous
#include <cuda_runtime.h>
#include <cuda_bf16.h>
#include <math.h>
#include <stdint.h>

#define N_NODES 100000
#define FEAT    256
#define HEADS   8
#define HEAD_DIM 32
#define E_EDGES 800000
#define SMAX    56

// ---------------- scratch (no cudaMalloc allowed) ----------------
__device__ float g_q[(size_t)N_NODES * FEAT];
__device__ float g_k[(size_t)N_NODES * FEAT];
__device__ float g_v[(size_t)N_NODES * FEAT];
__device__ __nv_bfloat16 g_a2[(size_t)N_NODES * 512];
__device__ __nv_bfloat16 g_acc2[(size_t)N_NODES * 512];
__device__ __nv_bfloat16 g_w2[4][(size_t)256 * 768];
// edge sort
__device__ int g_cnt[N_NODES];
__device__ int g_incl[N_NODES];
__device__ int g_off[N_NODES + 1];
__device__ int g_cur[N_NODES];
__device__ int g_srcs[E_EDGES];
__device__ float g_biasp[(size_t)E_EDGES * HEADS];
__device__ int g_bsum[128];

// ================= PTX helpers =================
__device__ __forceinline__ uint32_t smem_to_u32(const void* p) {
    uint32_t a;
    asm("{ .reg .u64 t; cvta.to.shared.u64 t, %1; cvt.u32.u64 %0, t; }" : "=r"(a) : "l"(p));
    return a;
}

#define LDSM_X4(r0, r1, r2, r3, addr) \
    asm volatile("ldmatrix.sync.aligned.m8n8.x4.shared.b16 {%0,%1,%2,%3}, [%4];" \
        : "=r"(r0), "=r"(r1), "=r"(r2), "=r"(r3) : "r"(addr))

#define MMA_16816(c, a0, a1, a2, a3, b0, b1) \
    asm volatile("mma.sync.aligned.m16n8k16.row.col.f32.bf16.bf16.f32 " \
        "{%0,%1,%2,%3}, {%4,%5,%6,%7}, {%8,%9}, {%0,%1,%2,%3};" \
        : "+f"((c)[0]), "+f"((c)[1]), "+f"((c)[2]), "+f"((c)[3]) \
        : "r"(a0), "r"(a1), "r"(a2), "r"(a3), "r"(b0), "r"(b1))

__device__ __forceinline__ void cp_async16(uint32_t dst, const void* src, uint32_t src_size) {
    asm volatile("cp.async.cg.shared.global [%0], [%1], 16, %2;"
        :: "r"(dst), "l"(src), "r"(src_size) : "memory");
}
#define CP_ASYNC_COMMIT() asm volatile("cp.async.commit_group;" ::: "memory")
#define CP_ASYNC_WAIT_GROUP(n) asm volatile("cp.async.wait_group %0;" :: "n"(n) : "memory")

// ---------------- fp32 -> bf16 hi/lo split (nodes), row range [r0,r1) ----------------
__global__ void conv_split_kernel(const float* __restrict__ X,
                                  __nv_bfloat16* __restrict__ Y,
                                  int r0, int r1) {
    int i = r0 * 64 + blockIdx.x * blockDim.x + threadIdx.x;
    if (i >= r1 * 64) return;
    int row = i >> 6, qq = i & 63;
    float4 x = ((const float4*)X)[i];
    __nv_bfloat16 h0 = __float2bfloat16(x.x), h1 = __float2bfloat16(x.y);
    __nv_bfloat16 h2 = __float2bfloat16(x.z), h3 = __float2bfloat16(x.w);
    __nv_bfloat16 l0 = __float2bfloat16(x.x - __bfloat162float(h0));
    __nv_bfloat16 l1 = __float2bfloat16(x.y - __bfloat162float(h1));
    __nv_bfloat16 l2 = __float2bfloat16(x.z - __bfloat162float(h2));
    __nv_bfloat16 l3 = __float2bfloat16(x.w - __bfloat162float(h3));
    uint32_t hA = ((uint32_t)__bfloat16_as_ushort(h1) << 16) | __bfloat16_as_ushort(h0);
    uint32_t hB = ((uint32_t)__bfloat16_as_ushort(h3) << 16) | __bfloat16_as_ushort(h2);
    uint32_t lA = ((uint32_t)__bfloat16_as_ushort(l1) << 16) | __bfloat16_as_ushort(l0);
    uint32_t lB = ((uint32_t)__bfloat16_as_ushort(l3) << 16) | __bfloat16_as_ushort(l2);
    size_t base = (size_t)row * 512 + qq * 4;
    *(uint2*)(Y + base)       = make_uint2(hA, hB);
    *(uint2*)(Y + base + 256) = make_uint2(lA, lB);
}

// ---------------- W -> W' = [Whi | Wlo | Whi], 4 mats fused ----------------
__global__ void conv_w_kernel(const float* __restrict__ W0, const float* __restrict__ W1,
                              const float* __restrict__ W2p, const float* __restrict__ W3,
                              __nv_bfloat16* __restrict__ OUT) {
    int i = blockIdx.x * blockDim.x + threadIdx.x;
    if (i >= 256 * 768) return;
    int which = blockIdx.y;
    const float* W = (which == 0) ? W0 : (which == 1) ? W1 : (which == 2) ? W2p : W3;
    int n = i / 768, kc = i % 768;
    int sk = (kc < 256) ? kc : ((kc < 512) ? kc - 256 : kc - 512);
    float w = W[n * 256 + sk];
    __nv_bfloat16 hi = __float2bfloat16(w);
    __nv_bfloat16 res;
    if (kc < 256 || kc >= 512) res = hi;
    else res = __float2bfloat16(w - __bfloat162float(hi));
    OUT[(size_t)which * 256 * 768 + (size_t)n * 768 + kc] = res;
}

// ---------------- HMMA GEMM (multi-output): gridDim.x = 2*nmat, 3-stage pipeline ----------------
#define NCHUNK 12
#define ROWB   144
#define ATILE  (128 * ROWB)
#define STAGE  (2 * ATILE)
#define GSMEM_BYTES (3 * STAGE)

__global__ __launch_bounds__(256, 2) void gemm_mma_kernel(
        const __nv_bfloat16* __restrict__ A2,
        const __nv_bfloat16* __restrict__ Wall,
        float* __restrict__ C0, float* __restrict__ C1, float* __restrict__ C2,
        int M, float scale0, int rowbase) {
    extern __shared__ __align__(16) char smem[];
    const uint32_t sbase = smem_to_u32(smem);

    const int tid = threadIdx.x;
    const int lane = tid & 31;
    const int wid = tid >> 5;
    const int warp_m = wid & 3;
    const int warp_n = wid >> 2;
    const int row0 = rowbase + blockIdx.y * 128;
    const int wsel = blockIdx.x >> 1;
    const int col0 = (blockIdx.x & 1) * 128;
    const __nv_bfloat16* W2 = Wall + (size_t)wsel * 256 * 768;
    float* C = (wsel == 0) ? C0 : ((wsel == 1) ? C1 : C2);
    const float outScale = (wsel == 0) ? scale0 : 1.0f;

    const int lq = tid & 7;
    const int lr0 = tid >> 3;

    const uint32_t a_off = (uint32_t)((lane & 15) * ROWB + ((lane & 16) ? 16 : 0));
    const uint32_t b_off = (uint32_t)(((lane & 7) + ((lane & 16) ? 8 : 0)) * ROWB +
                                      ((lane & 8) ? 16 : 0));

    float cfr[2][8][4];
#pragma unroll
    for (int mi = 0; mi < 2; mi++)
#pragma unroll
        for (int ni = 0; ni < 8; ni++)
#pragma unroll
            for (int j = 0; j < 4; j++) cfr[mi][ni][j] = 0.0f;

    auto issue_loads = [&](int c) {
        const int stage_idx = c % 3;
        const int srcoff = ((c < 8) ? 0 : 256) + (c & 3) * 64;
        const uint32_t sa = sbase + stage_idx * STAGE;
        const uint32_t sb = sa + ATILE;
#pragma unroll
        for (int it = 0; it < 4; it++) {
            int r = lr0 + it * 32;
            int gr = row0 + r;
            uint32_t ok = (gr < M) ? 16u : 0u;
            int grc = (gr < M) ? gr : 0;
            cp_async16(sa + r * ROWB + lq * 16,
                       A2 + (size_t)grc * 512 + srcoff + lq * 8, ok);
            cp_async16(sb + r * ROWB + lq * 16,
                       W2 + (size_t)(col0 + r) * 768 + c * 64 + lq * 8, 16u);
        }
        CP_ASYNC_COMMIT();
    };

    issue_loads(0);
    issue_loads(1);

    for (int c = 0; c < NCHUNK; c++) {
        CP_ASYNC_WAIT_GROUP(1);
        __syncthreads();
        if (c + 2 < NCHUNK) issue_loads(c + 2);

        const uint32_t sa = sbase + (c % 3) * STAGE + (warp_m * 32) * ROWB + a_off;
        const uint32_t sb = sbase + (c % 3) * STAGE + ATILE + (warp_n * 64) * ROWB + b_off;

#pragma unroll
        for (int kk = 0; kk < 4; kk++) {
            uint32_t a[2][4];
#pragma unroll
            for (int mi = 0; mi < 2; mi++)
                LDSM_X4(a[mi][0], a[mi][1], a[mi][2], a[mi][3],
                        sa + mi * 16 * ROWB + kk * 32);
            uint32_t b[4][4];
#pragma unroll
            for (int nt = 0; nt < 4; nt++)
                LDSM_X4(b[nt][0], b[nt][1], b[nt][2], b[nt][3],
                        sb + nt * 16 * ROWB + kk * 32);
#pragma unroll
            for (int mi = 0; mi < 2; mi++)
#pragma unroll
                for (int nt = 0; nt < 4; nt++) {
                    MMA_16816(cfr[mi][nt * 2 + 0],
                              a[mi][0], a[mi][1], a[mi][2], a[mi][3],
                              b[nt][0], b[nt][1]);
                    MMA_16816(cfr[mi][nt * 2 + 1],
                              a[mi][0], a[mi][1], a[mi][2], a[mi][3],
                              b[nt][2], b[nt][3]);
                }
        }
    }

    const int rbase = row0 + warp_m * 32 + (lane >> 2);
    const int cbase = col0 + warp_n * 64 + (lane & 3) * 2;
#pragma unroll
    for (int mi = 0; mi < 2; mi++) {
#pragma unroll
        for (int ni = 0; ni < 8; ni++) {
            int r = rbase + mi * 16;
            int cc = cbase + ni * 8;
            if (r < M) {
                float2 o0 = make_float2(cfr[mi][ni][0] * outScale, cfr[mi][ni][1] * outScale);
                *(float2*)&C[(size_t)r * FEAT + cc] = o0;
            }
            if (r + 8 < M) {
                float2 o1 = make_float2(cfr[mi][ni][2] * outScale, cfr[mi][ni][3] * outScale);
                *(float2*)&C[(size_t)(r + 8) * FEAT + cc] = o1;
            }
        }
    }
}

// ================= edge sort: counting sort by dst =================
__global__ void zero_cnt_kernel(int* cnt, int n) {
    int i = blockIdx.x * blockDim.x + threadIdx.x;
    if (i < n) cnt[i] = 0;
}
__global__ void hist_kernel(const int* __restrict__ dst, int* cnt, int E) {
    int e = blockIdx.x * blockDim.x + threadIdx.x;
    if (e < E) atomicAdd(&cnt[dst[e]], 1);
}
__global__ void scan1_kernel(const int* __restrict__ cnt, int* incl, int* bsum, int n) {
    __shared__ int sm[1024];
    int i = blockIdx.x * 1024 + threadIdx.x;
    int val = (i < n) ? cnt[i] : 0;
    sm[threadIdx.x] = val;
    __syncthreads();
#pragma unroll
    for (int off = 1; off < 1024; off <<= 1) {
        int t = (threadIdx.x >= off) ? sm[threadIdx.x - off] : 0;
        __syncthreads();
        sm[threadIdx.x] += t;
        __syncthreads();
    }
    if (i < n) incl[i] = sm[threadIdx.x];
    if (threadIdx.x == 1023) bsum[blockIdx.x] = sm[1023];
}
__global__ void scan2_kernel(int* bsum, int nb) {
    __shared__ int sm[128];
    int t = threadIdx.x;
    int v = (t < nb) ? bsum[t] : 0;
    sm[t] = v;
    __syncthreads();
#pragma unroll
    for (int off = 1; off < 128; off <<= 1) {
        int u = (t >= off) ? sm[t - off] : 0;
        __syncthreads();
        sm[t] += u;
        __syncthreads();
    }
    if (t < nb) bsum[t] = sm[t] - v;
}
__global__ void scan3_kernel(const int* __restrict__ incl, const int* __restrict__ bsum,
                             const int* __restrict__ cnt, int* off, int* cur, int n) {
    int i = blockIdx.x * blockDim.x + threadIdx.x;
    if (i == 0) off[0] = 0;
    if (i < n) {
        int o = incl[i] + bsum[i >> 10];
        off[i + 1] = o;
        cur[i] = o - cnt[i];
    }
}
// scatter + fused bias permutation (bias read coalesced in e, scattered write)
__global__ void scatter_kernel(const int* __restrict__ dst, const int* __restrict__ src,
                               const float* __restrict__ bias,
                               int* cur, int* srcs, float* __restrict__ biasp, int E) {
    int e = blockIdx.x * blockDim.x + threadIdx.x;
    if (e < E) {
        int pos = atomicAdd(&cur[dst[e]], 1);
        srcs[pos] = src[e];
        float4 b0 = *(const float4*)(bias + (size_t)e * HEADS);
        float4 b1 = *(const float4*)(bias + (size_t)e * HEADS + 4);
        *(float4*)(biasp + (size_t)pos * HEADS)     = b0;
        *(float4*)(biasp + (size_t)pos * HEADS + 4) = b1;
    }
}

// ================= fused edge kernel: warp per dst, TWO-PASS (round-9 optimum) =================
__global__ __launch_bounds__(256) void edge_fused_kernel(
        const float* __restrict__ q,
        const float* __restrict__ k,
        const float* __restrict__ v,
        const float* __restrict__ biasp,
        const int* __restrict__ srcs,
        const int* __restrict__ off,
        __nv_bfloat16* __restrict__ acc2,
        int N) {
    __shared__ float slog[8][SMAX * 8];
    const unsigned FULL = 0xffffffffu;
    int gw = (int)((blockIdx.x * (size_t)blockDim.x + threadIdx.x) >> 5);
    int lane = threadIdx.x & 31;
    int wib = threadIdx.x >> 5;
    if (gw >= N) return;
    const int d = gw;
    const int beg = off[d], end = off[d + 1];
    const int deg = end - beg;
    const int h = lane >> 2;

    const float4* qp = (const float4*)(q + (size_t)d * FEAT);
    float4 q0, q1;
    float mh = -INFINITY;
    const bool fits = (deg <= SMAX);

    if (deg > 0) {
        q0 = qp[lane * 2];
        q1 = qp[lane * 2 + 1];
        for (int base = 0; base < deg; base += 32) {
            int cnt = min(32, deg - base);
            int s_l = 0;
            if (lane < cnt) s_l = __ldg(&srcs[beg + base + lane]);
            for (int i = 0; i < cnt; i++) {
                int sn = __shfl_sync(FULL, s_l, i);
                const float4* kp = (const float4*)(k + (size_t)sn * FEAT);
                float4 k0 = kp[lane * 2], k1 = kp[lane * 2 + 1];
                float ds = q0.x * k0.x + q0.y * k0.y + q0.z * k0.z + q0.w * k0.w
                         + q1.x * k1.x + q1.y * k1.y + q1.z * k1.z + q1.w * k1.w;
                ds += __shfl_xor_sync(FULL, ds, 1);
                ds += __shfl_xor_sync(FULL, ds, 2);
                float l = ds + __ldg(&biasp[(size_t)(beg + base + i) * HEADS + h]);
                mh = fmaxf(mh, l);
                if (fits && (lane & 3) == 0) slog[wib][(base + i) * 8 + h] = l;
            }
        }
    }

    float acc[8] = {0, 0, 0, 0, 0, 0, 0, 0};
    float ssum = 0.0f;
    for (int base = 0; base < deg; base += 32) {
        int cnt = min(32, deg - base);
        int s_l = 0;
        if (lane < cnt) s_l = __ldg(&srcs[beg + base + lane]);
        for (int i = 0; i < cnt; i++) {
            int sn = __shfl_sync(FULL, s_l, i);
            float l;
            if (fits) {
                l = slog[wib][(base + i) * 8 + h];
            } else {
                const float4* kp = (const float4*)(k + (size_t)sn * FEAT);
                float4 k0 = kp[lane * 2], k1 = kp[lane * 2 + 1];
                float ds = q0.x * k0.x + q0.y * k0.y + q0.z * k0.z + q0.w * k0.w
                         + q1.x * k1.x + q1.y * k1.y + q1.z * k1.z + q1.w * k1.w;
                ds += __shfl_xor_sync(FULL, ds, 1);
                ds += __shfl_xor_sync(FULL, ds, 2);
                l = ds + __ldg(&biasp[(size_t)(beg + base + i) * HEADS + h]);
            }
            float a = __expf(l - mh);
            ssum += a;
            const float4* vp = (const float4*)(v + (size_t)sn * FEAT);
            float4 v0 = vp[lane * 2], v1 = vp[lane * 2 + 1];
            acc[0] = fmaf(a, v0.x, acc[0]);
            acc[1] = fmaf(a, v0.y, acc[1]);
            acc[2] = fmaf(a, v0.z, acc[2]);
            acc[3] = fmaf(a, v0.w, acc[3]);
            acc[4] = fmaf(a, v1.x, acc[4]);
            acc[5] = fmaf(a, v1.y, acc[5]);
            acc[6] = fmaf(a, v1.z, acc[6]);
            acc[7] = fmaf(a, v1.w, acc[7]);
        }
    }

    float r = (deg > 0) ? (1.0f / ssum) : 0.0f;

    float o[8];
#pragma unroll
    for (int j = 0; j < 8; j++) o[j] = acc[j] * r;
    __nv_bfloat16 hi[8], lo[8];
#pragma unroll
    for (int j = 0; j < 8; j++) {
        hi[j] = __float2bfloat16(o[j]);
        lo[j] = __float2bfloat16(o[j] - __bfloat162float(hi[j]));
    }
    uint4 hv, lv;
    hv.x = ((uint32_t)__bfloat16_as_ushort(hi[1]) << 16) | __bfloat16_as_ushort(hi[0]);
    hv.y = ((uint32_t)__bfloat16_as_ushort(hi[3]) << 16) | __bfloat16_as_ushort(hi[2]);
    hv.z = ((uint32_t)__bfloat16_as_ushort(hi[5]) << 16) | __bfloat16_as_ushort(hi[4]);
    hv.w = ((uint32_t)__bfloat16_as_ushort(hi[7]) << 16) | __bfloat16_as_ushort(hi[6]);
    lv.x = ((uint32_t)__bfloat16_as_ushort(lo[1]) << 16) | __bfloat16_as_ushort(lo[0]);
    lv.y = ((uint32_t)__bfloat16_as_ushort(lo[3]) << 16) | __bfloat16_as_ushort(lo[2]);
    lv.z = ((uint32_t)__bfloat16_as_ushort(lo[5]) << 16) | __bfloat16_as_ushort(lo[4]);
    lv.w = ((uint32_t)__bfloat16_as_ushort(lo[7]) << 16) | __bfloat16_as_ushort(lo[6]);
    *(uint4*)(acc2 + (size_t)d * 512 + lane * 8)       = hv;
    *(uint4*)(acc2 + (size_t)d * 512 + 256 + lane * 8) = lv;
}

// ---------------- launch ----------------
extern "C" void kernel_launch(void* const* d_in, const int* in_sizes, int n_in,
                              void* d_out, int out_size) {
    const float* nfeat = (const float*)d_in[0];
    const float* attn_bias = (const float*)d_in[1];
    const float* Wq = (const float*)d_in[2];
    const float* Wk = (const float*)d_in[3];
    const float* Wv = (const float*)d_in[4];
    const float* Wo = (const float*)d_in[5];
    const int* src = (const int*)d_in[6];
    const int* dst = (const int*)d_in[7];
    float* out = (float*)d_out;

    int N = in_sizes[0] / FEAT;
    int E = in_sizes[6];

    float *q, *k, *v, *biasp;
    __nv_bfloat16 *a2, *acc2, *w2;
    int *cnt, *incl, *off, *cur, *srcs, *bsum;
    cudaGetSymbolAddress((void**)&q, g_q);
    cudaGetSymbolAddress((void**)&k, g_k);
    cudaGetSymbolAddress((void**)&v, g_v);
    cudaGetSymbolAddress((void**)&a2, g_a2);
    cudaGetSymbolAddress((void**)&acc2, g_acc2);
    cudaGetSymbolAddress((void**)&w2, g_w2);
    cudaGetSymbolAddress((void**)&cnt, g_cnt);
    cudaGetSymbolAddress((void**)&incl, g_incl);
    cudaGetSymbolAddress((void**)&off, g_off);
    cudaGetSymbolAddress((void**)&cur, g_cur);
    cudaGetSymbolAddress((void**)&srcs, g_srcs);
    cudaGetSymbolAddress((void**)&biasp, g_biasp);
    cudaGetSymbolAddress((void**)&bsum, g_bsum);

    cudaFuncSetAttribute(gemm_mma_kernel, cudaFuncAttributeMaxDynamicSharedMemorySize, GSMEM_BYTES);

    static cudaStream_t s_sort = nullptr, s_og = nullptr;
    static cudaEvent_t ev_fork = nullptr, ev_join = nullptr, ev_w = nullptr;
    static cudaEvent_t ev_c0 = nullptr, ev_g0 = nullptr;
    if (!s_sort) {
        cudaStreamCreateWithFlags(&s_sort, cudaStreamNonBlocking);
        cudaStreamCreateWithFlags(&s_og, cudaStreamNonBlocking);
        cudaEventCreateWithFlags(&ev_fork, cudaEventDisableTiming);
        cudaEventCreateWithFlags(&ev_join, cudaEventDisableTiming);
        cudaEventCreateWithFlags(&ev_w, cudaEventDisableTiming);
        cudaEventCreateWithFlags(&ev_c0, cudaEventDisableTiming);
        cudaEventCreateWithFlags(&ev_g0, cudaEventDisableTiming);
    }

    // ---- fork: conv_w first (needed by QKV GEMM), then sort chain on side stream ----
    cudaEventRecord(ev_fork, 0);
    cudaStreamWaitEvent(s_sort, ev_fork, 0);
    dim3 wgrid((256 * 768 + 255) / 256, 4);
    conv_w_kernel<<<wgrid, 256, 0, s_sort>>>(Wq, Wk, Wv, Wo, w2);
    cudaEventRecord(ev_w, s_sort);
    int nb1024 = (N + 1023) / 1024;
    zero_cnt_kernel<<<(N + 255) / 256, 256, 0, s_sort>>>(cnt, N);
    hist_kernel<<<(E + 255) / 256, 256, 0, s_sort>>>(dst, cnt, E);
    scan1_kernel<<<nb1024, 1024, 0, s_sort>>>(cnt, incl, bsum, N);
    scan2_kernel<<<1, 128, 0, s_sort>>>(bsum, nb1024);
    scan3_kernel<<<(N + 255) / 256, 256, 0, s_sort>>>(incl, bsum, cnt, off, cur, N);
    scatter_kernel<<<(E + 255) / 256, 256, 0, s_sort>>>(dst, src, attn_bias, cur, srcs, biasp, E);
    cudaEventRecord(ev_join, s_sort);

    // ---- main: conv_split half 0, then half 1; QKV GEMM split across two streams ----
    const int H0 = 50048;                    // multiple of 128
    int h0 = (N < H0) ? N : H0;
    int h1r = N - h0;                        // remaining rows

    conv_split_kernel<<<(h0 * 64 + 255) / 256, 256>>>(nfeat, a2, 0, h0);
    cudaEventRecord(ev_c0, 0);
    if (h1r > 0)
        conv_split_kernel<<<(h1r * 64 + 255) / 256, 256>>>(nfeat, a2, h0, N);

    const float invScaling = 5.656854249492381f;  // sqrt(HEAD_DIM): reference DIVIDES q by scaling

    // GEMM(rows [0,h0)) on s_og as soon as conv(h0) + conv_w done
    cudaStreamWaitEvent(s_og, ev_c0, 0);
    cudaStreamWaitEvent(s_og, ev_w, 0);
    dim3 qg0(6, (h0 + 127) / 128);
    gemm_mma_kernel<<<qg0, 256, GSMEM_BYTES, s_og>>>(a2, w2, q, k, v, N, invScaling, 0);
    cudaEventRecord(ev_g0, s_og);

    // GEMM(rows [h0,N)) on main after conv(h1) (+ conv_w)
    cudaStreamWaitEvent(0, ev_w, 0);
    if (h1r > 0) {
        dim3 qg1(6, (h1r + 127) / 128);
        gemm_mma_kernel<<<qg1, 256, GSMEM_BYTES>>>(a2, w2, q, k, v, N, invScaling, h0);
    }

    // ---- join: both GEMM halves + sort before edge kernel ----
    cudaStreamWaitEvent(0, ev_g0, 0);
    cudaStreamWaitEvent(0, ev_join, 0);

    // ---- fused edge softmax + aggregate (two-pass) ----
    int fblocks = (N + 7) / 8;
    edge_fused_kernel<<<fblocks, 256>>>(q, k, v, biasp, srcs, off, acc2, N);

    // ---- final projection (single matrix: Wo slot) ----
    dim3 ogrid(2, (N + 127) / 128);
    gemm_mma_kernel<<<ogrid, 256, GSMEM_BYTES>>>(acc2, w2 + 3 * (size_t)256 * 768,
                                                 out, nullptr, nullptr, N, 1.0f, 0);
}